// round 1
// baseline (speedup 1.0000x reference)
#include <cuda_runtime.h>
#include <cstdint>
#include <cstddef>

#define BB 64
#define TT 512
#define II 128
#define HH 512
#define NCLS 5

typedef unsigned long long u64;

// Scratch (64 MB each) — static __device__ arrays per allocation rules.
__device__ float g_xp[(size_t)BB * TT * HH];
__device__ float g_ys[(size_t)BB * TT * HH];

// ---------------- packed f32x2 helpers ----------------
__device__ __forceinline__ u64 pk2(float x, float y) {
    u64 r; asm("mov.b64 %0, {%1,%2};" : "=l"(r) : "f"(x), "f"(y)); return r;
}
__device__ __forceinline__ float2 upk2(u64 v) {
    float2 f; asm("mov.b64 {%0,%1}, %2;" : "=f"(f.x), "=f"(f.y) : "l"(v)); return f;
}
__device__ __forceinline__ void fma2(u64 &d, u64 a, u64 b) {
    asm("fma.rn.f32x2 %0, %1, %2, %0;" : "+l"(d) : "l"(a), "l"(b));
}

// =======================================================================
// GEMM: C[M][HH] = A[M][K] @ W[HH][K]^T + b1 + b2
// BM=BN=128, BK=16, 256 threads, 8x8 strided thread tile, f32x2 over k-pairs.
// =======================================================================
__global__ void __launch_bounds__(256, 1)
gemm_xproj(const float* __restrict__ A, const float* __restrict__ W,
           const float* __restrict__ b1, const float* __restrict__ b2,
           float* __restrict__ C, int K)
{
    __shared__ u64 As2[8][128];  // [k2][row], each u64 = {A[r][2k2], A[r][2k2+1]}
    __shared__ u64 Bs2[8][128];  // [k2][col]

    const int tid = threadIdx.x;
    const int m0 = blockIdx.y * 128;
    const int n0 = blockIdx.x * 128;
    const int tx = tid & 15;      // col = tx + 16*j
    const int ty = tid >> 4;      // row = ty + 16*i

    const int r0  = tid >> 2;     // 0..63  (loader row)
    const int kq0 = tid & 3;      // 0..3   (float4 chunk along k)

    u64 acc[8][8];
    #pragma unroll
    for (int i = 0; i < 8; i++)
        #pragma unroll
        for (int j = 0; j < 8; j++) acc[i][j] = 0ull;

    const int ktiles = K >> 4;
    for (int kt = 0; kt < ktiles; kt++) {
        const int kb = kt * 16;
        // global loads (overlap previous tile's compute via the syncthreads below)
        float4 a0 = *(const float4*)&A[(size_t)(m0 + r0)      * K + kb + kq0 * 4];
        float4 a1 = *(const float4*)&A[(size_t)(m0 + 64 + r0) * K + kb + kq0 * 4];
        float4 w0 = *(const float4*)&W[(size_t)(n0 + r0)      * K + kb + kq0 * 4];
        float4 w1 = *(const float4*)&W[(size_t)(n0 + 64 + r0) * K + kb + kq0 * 4];
        __syncthreads();
        As2[kq0 * 2][r0]          = pk2(a0.x, a0.y);
        As2[kq0 * 2 + 1][r0]      = pk2(a0.z, a0.w);
        As2[kq0 * 2][64 + r0]     = pk2(a1.x, a1.y);
        As2[kq0 * 2 + 1][64 + r0] = pk2(a1.z, a1.w);
        Bs2[kq0 * 2][r0]          = pk2(w0.x, w0.y);
        Bs2[kq0 * 2 + 1][r0]      = pk2(w0.z, w0.w);
        Bs2[kq0 * 2][64 + r0]     = pk2(w1.x, w1.y);
        Bs2[kq0 * 2 + 1][64 + r0] = pk2(w1.z, w1.w);
        __syncthreads();

        #pragma unroll
        for (int k2 = 0; k2 < 8; k2++) {
            u64 af[8], bf[8];
            #pragma unroll
            for (int i = 0; i < 8; i++) af[i] = As2[k2][ty + 16 * i];
            #pragma unroll
            for (int j = 0; j < 8; j++) bf[j] = Bs2[k2][tx + 16 * j];
            #pragma unroll
            for (int i = 0; i < 8; i++)
                #pragma unroll
                for (int j = 0; j < 8; j++)
                    fma2(acc[i][j], af[i], bf[j]);
        }
    }

    float bias8[8];
    #pragma unroll
    for (int j = 0; j < 8; j++) {
        int n = n0 + tx + 16 * j;
        bias8[j] = b1[n] + b2[n];
    }
    #pragma unroll
    for (int i = 0; i < 8; i++) {
        const size_t m = (size_t)(m0 + ty + 16 * i);
        #pragma unroll
        for (int j = 0; j < 8; j++) {
            float2 p = upk2(acc[i][j]);
            C[m * HH + n0 + tx + 16 * j] = p.x + p.y + bias8[j];
        }
    }
}

// =======================================================================
// Recurrence: ys[b][t][:] = relu(xp[b][t][:] + W_hh @ h_{t-1}[b])
// 16 clusters x 8 CTAs. Cluster owns 4 batch chains; CTA owns 64 output cols.
// W slice pinned in registers (k-pair packed), cluster barrier per step.
// =======================================================================
__global__ void __launch_bounds__(256, 1) __cluster_dims__(8, 1, 1)
rnn_recur(const float* __restrict__ xp, const float* __restrict__ Whh,
          float* __restrict__ ys)
{
    __shared__ ulonglong2 h_s[4][HH / 4];   // [b][k4] : 16B = 2 k-pairs = 4 floats
    __shared__ float4 redv[8][64];          // [kc][jlocal] : components = b 0..3

    const int tid   = threadIdx.x;
    const int r     = blockIdx.x & 7;       // cluster rank
    const int cl    = blockIdx.x >> 3;      // cluster id
    const int bg    = cl * 4;               // first batch of this cluster
    const int jbase = r * 64;               // first output col of this CTA

    const int jp = tid & 31;                // col-pair slot (j, j+32)
    const int kc = tid >> 5;                // k-chunk 0..7 (64 k each)
    const int k0 = kc * 64;

    // ---- load W_hh slice into registers, packed by k-pairs ----
    u64 w[2][32];
    #pragma unroll
    for (int jj = 0; jj < 2; jj++) {
        const float* wrow = &Whh[(size_t)(jbase + jp + jj * 32) * HH + k0];
        #pragma unroll
        for (int kp = 0; kp < 32; kp++) {
            float2 wv = *(const float2*)&wrow[2 * kp];
            w[jj][kp] = pk2(wv.x, wv.y);
        }
    }

    // ---- h0 = 0 ----
    {
        float4* hs = (float4*)h_s;
        for (int i = tid; i < 4 * (HH / 4); i += 256)
            hs[i] = make_float4(0.f, 0.f, 0.f, 0.f);
    }
    __syncthreads();

    // consumer mapping: one output scalar per thread
    const int cb = tid & 3;                 // batch
    const int cj = tid >> 2;                // local col 0..63
    const float* xp_ptr = &xp[((size_t)(bg + cb) * TT) * HH + jbase + cj];
    float*       ys_ptr = &ys[((size_t)(bg + cb) * TT) * HH + jbase + cj];

    // h reload mapping
    const int hb0 = tid >> 7;               // 0..1
    const int hi0 = tid & 127;              // float4 index within row

    for (int t = 0; t < TT; t++) {
        // prefetch xproj for this step (consumed after ~1024-cyc compute)
        const float xpv = __ldg(xp_ptr);

        // ---- compute partial GEMM: all W from regs, h broadcast from smem ----
        u64 acc0[4], acc1[4];
        #pragma unroll
        for (int b = 0; b < 4; b++) {
            u64 a0 = 0ull, a1 = 0ull;
            #pragma unroll
            for (int kv = 0; kv < 16; kv++) {
                ulonglong2 hv = h_s[b][kc * 16 + kv];   // 4 floats = 2 k-pairs
                fma2(a0, w[0][2 * kv],     hv.x);
                fma2(a0, w[0][2 * kv + 1], hv.y);
                fma2(a1, w[1][2 * kv],     hv.x);
                fma2(a1, w[1][2 * kv + 1], hv.y);
            }
            acc0[b] = a0; acc1[b] = a1;
        }

        // ---- smem reduction across 8 k-chunks ----
        {
            float4 v0, v1;
            float2 p;
            p = upk2(acc0[0]); v0.x = p.x + p.y;
            p = upk2(acc0[1]); v0.y = p.x + p.y;
            p = upk2(acc0[2]); v0.z = p.x + p.y;
            p = upk2(acc0[3]); v0.w = p.x + p.y;
            p = upk2(acc1[0]); v1.x = p.x + p.y;
            p = upk2(acc1[1]); v1.y = p.x + p.y;
            p = upk2(acc1[2]); v1.z = p.x + p.y;
            p = upk2(acc1[3]); v1.w = p.x + p.y;
            redv[kc][jp]      = v0;
            redv[kc][jp + 32] = v1;
        }
        __syncthreads();

        {
            const float* rp = (const float*)redv;
            float s = 0.f;
            #pragma unroll
            for (int c = 0; c < 8; c++) s += rp[c * 256 + cj * 4 + cb];
            s += xpv;
            s = fmaxf(s, 0.f);
            __stcg(ys_ptr, s);               // L2-visible for peer CTAs
        }

        // cluster barrier: release my h slice, acquire peers'
        asm volatile("barrier.cluster.arrive.aligned;" ::: "memory");
        asm volatile("barrier.cluster.wait.aligned;"   ::: "memory");

        // ---- reload full h_t (4 rows x 512) from L2 into smem ----
        {
            const float4* s0 = (const float4*)&ys[(((size_t)(bg + hb0)     * TT + t) * HH)];
            const float4* s1 = (const float4*)&ys[(((size_t)(bg + 2 + hb0) * TT + t) * HH)];
            float4 v0 = __ldcg(s0 + hi0);
            float4 v1 = __ldcg(s1 + hi0);
            ((float4*)h_s)[hb0 * 128 + hi0]       = v0;
            ((float4*)h_s)[(2 + hb0) * 128 + hi0] = v1;
        }
        __syncthreads();

        xp_ptr += HH;
        ys_ptr += HH;
    }
}

// =======================================================================
// Final projection: out[b][c] = ys[b][T-1][:] . W_out[c][:] + b_out[c]
// =======================================================================
__global__ void proj_kernel(const float* __restrict__ ys,
                            const float* __restrict__ Wout,
                            const float* __restrict__ bout,
                            float* __restrict__ out)
{
    const int b    = blockIdx.x;
    const int c    = threadIdx.y;    // 0..4
    const int lane = threadIdx.x;    // 0..31
    const float* hrow = &ys[((size_t)b * TT + (TT - 1)) * HH];
    const float* wrow = &Wout[(size_t)c * HH];
    float s = 0.f;
    for (int k = lane; k < HH; k += 32) s += hrow[k] * wrow[k];
    #pragma unroll
    for (int o = 16; o > 0; o >>= 1) s += __shfl_down_sync(0xffffffffu, s, o);
    if (lane == 0) out[b * NCLS + c] = s + bout[c];
}

// =======================================================================
extern "C" void kernel_launch(void* const* d_in, const int* in_sizes, int n_in,
                              void* d_out, int out_size)
{
    (void)in_sizes; (void)n_in; (void)out_size;
    const float* x    = (const float*)d_in[0];
    const float* Wih[3] = {(const float*)d_in[1], (const float*)d_in[5], (const float*)d_in[9]};
    const float* Whh[3] = {(const float*)d_in[2], (const float*)d_in[6], (const float*)d_in[10]};
    const float* bih[3] = {(const float*)d_in[3], (const float*)d_in[7], (const float*)d_in[11]};
    const float* bhh[3] = {(const float*)d_in[4], (const float*)d_in[8], (const float*)d_in[12]};
    const float* Wout = (const float*)d_in[13];
    const float* bout = (const float*)d_in[14];
    float* out = (float*)d_out;

    float *xpPtr = nullptr, *ysPtr = nullptr;
    cudaGetSymbolAddress((void**)&xpPtr, g_xp);
    cudaGetSymbolAddress((void**)&ysPtr, g_ys);

    const dim3 ggrid(HH / 128, (BB * TT) / 128);
    for (int l = 0; l < 3; l++) {
        const float* A = (l == 0) ? x : ysPtr;
        const int K = (l == 0) ? II : HH;
        gemm_xproj<<<ggrid, 256>>>(A, Wih[l], bih[l], bhh[l], xpPtr, K);
        rnn_recur<<<128, 256>>>(xpPtr, Whh[l], ysPtr);
    }
    proj_kernel<<<64, dim3(32, 5)>>>(ysPtr, Wout, bout, out);
}

// round 2
// speedup vs baseline: 1.1565x; 1.1565x over previous
#include <cuda_runtime.h>
#include <cstdint>
#include <cstddef>

#define BB 64
#define TT 512
#define II 128
#define HH 512
#define NCLS 5

typedef unsigned long long u64;

// Scratch — static __device__ arrays per allocation rules.
__device__ float g_xp[(size_t)BB * TT * HH];
__device__ float g_ys[(size_t)BB * TT * HH];

// ---------------- packed f32x2 helpers ----------------
__device__ __forceinline__ u64 pk2(float x, float y) {
    u64 r; asm("mov.b64 %0, {%1,%2};" : "=l"(r) : "f"(x), "f"(y)); return r;
}
__device__ __forceinline__ float2 upk2(u64 v) {
    float2 f; asm("mov.b64 {%0,%1}, %2;" : "=f"(f.x), "=f"(f.y) : "l"(v)); return f;
}
__device__ __forceinline__ void fma2(u64 &d, u64 a, u64 b) {
    asm("fma.rn.f32x2 %0, %1, %2, %0;" : "+l"(d) : "l"(a), "l"(b));
}

// ---------------- cluster / mbarrier helpers ----------------
__device__ __forceinline__ uint32_t smem_u32(const void* p) {
    uint32_t a;
    asm("{ .reg .u64 t; cvta.to.shared.u64 t, %1; cvt.u32.u64 %0, t; }"
        : "=r"(a) : "l"(p));
    return a;
}
__device__ __forceinline__ uint32_t mapa_u32(uint32_t local, uint32_t rank) {
    uint32_t r;
    asm("mapa.shared::cluster.u32 %0, %1, %2;" : "=r"(r) : "r"(local), "r"(rank));
    return r;
}
__device__ __forceinline__ void st_dsmem4(uint32_t addr, float4 v) {
    asm volatile("st.shared::cluster.v4.f32 [%0], {%1,%2,%3,%4};"
                 :: "r"(addr), "f"(v.x), "f"(v.y), "f"(v.z), "f"(v.w) : "memory");
}
__device__ __forceinline__ void mbar_init(uint32_t addr, uint32_t count) {
    asm volatile("mbarrier.init.shared.b64 [%0], %1;" :: "r"(addr), "r"(count) : "memory");
}
__device__ __forceinline__ void mbar_arrive_remote(uint32_t remote_addr) {
    asm volatile("mbarrier.arrive.release.cluster.shared::cluster.b64 _, [%0];"
                 :: "r"(remote_addr) : "memory");
}
__device__ __forceinline__ void mbar_wait_cluster(uint32_t addr, uint32_t parity) {
    asm volatile(
        "{\n\t"
        ".reg .pred P;\n\t"
        "WLP%=:\n\t"
        "mbarrier.try_wait.parity.acquire.cluster.shared::cta.b64 P, [%0], %1, 0x989680;\n\t"
        "@P bra WDN%=;\n\t"
        "bra WLP%=;\n\t"
        "WDN%=:\n\t"
        "}"
        :: "r"(addr), "r"(parity) : "memory");
}
__device__ __forceinline__ void cluster_sync_full() {
    asm volatile("barrier.cluster.arrive.aligned;" ::: "memory");
    asm volatile("barrier.cluster.wait.aligned;" ::: "memory");
}

// =======================================================================
// GEMM: C[M][HH] = A[M][K] @ W[HH][K]^T + b1 + b2
// =======================================================================
__global__ void __launch_bounds__(256, 1)
gemm_xproj(const float* __restrict__ A, const float* __restrict__ W,
           const float* __restrict__ b1, const float* __restrict__ b2,
           float* __restrict__ C, int K)
{
    __shared__ u64 As2[8][128];
    __shared__ u64 Bs2[8][128];

    const int tid = threadIdx.x;
    const int m0 = blockIdx.y * 128;
    const int n0 = blockIdx.x * 128;
    const int tx = tid & 15;
    const int ty = tid >> 4;

    const int r0  = tid >> 2;
    const int kq0 = tid & 3;

    u64 acc[8][8];
    #pragma unroll
    for (int i = 0; i < 8; i++)
        #pragma unroll
        for (int j = 0; j < 8; j++) acc[i][j] = 0ull;

    const int ktiles = K >> 4;
    for (int kt = 0; kt < ktiles; kt++) {
        const int kb = kt * 16;
        float4 a0 = *(const float4*)&A[(size_t)(m0 + r0)      * K + kb + kq0 * 4];
        float4 a1 = *(const float4*)&A[(size_t)(m0 + 64 + r0) * K + kb + kq0 * 4];
        float4 w0 = *(const float4*)&W[(size_t)(n0 + r0)      * K + kb + kq0 * 4];
        float4 w1 = *(const float4*)&W[(size_t)(n0 + 64 + r0) * K + kb + kq0 * 4];
        __syncthreads();
        As2[kq0 * 2][r0]          = pk2(a0.x, a0.y);
        As2[kq0 * 2 + 1][r0]      = pk2(a0.z, a0.w);
        As2[kq0 * 2][64 + r0]     = pk2(a1.x, a1.y);
        As2[kq0 * 2 + 1][64 + r0] = pk2(a1.z, a1.w);
        Bs2[kq0 * 2][r0]          = pk2(w0.x, w0.y);
        Bs2[kq0 * 2 + 1][r0]      = pk2(w0.z, w0.w);
        Bs2[kq0 * 2][64 + r0]     = pk2(w1.x, w1.y);
        Bs2[kq0 * 2 + 1][64 + r0] = pk2(w1.z, w1.w);
        __syncthreads();

        #pragma unroll
        for (int k2 = 0; k2 < 8; k2++) {
            u64 af[8], bf[8];
            #pragma unroll
            for (int i = 0; i < 8; i++) af[i] = As2[k2][ty + 16 * i];
            #pragma unroll
            for (int j = 0; j < 8; j++) bf[j] = Bs2[k2][tx + 16 * j];
            #pragma unroll
            for (int i = 0; i < 8; i++)
                #pragma unroll
                for (int j = 0; j < 8; j++)
                    fma2(acc[i][j], af[i], bf[j]);
        }
    }

    float bias8[8];
    #pragma unroll
    for (int j = 0; j < 8; j++) {
        int n = n0 + tx + 16 * j;
        bias8[j] = b1[n] + b2[n];
    }
    #pragma unroll
    for (int i = 0; i < 8; i++) {
        const size_t m = (size_t)(m0 + ty + 16 * i);
        #pragma unroll
        for (int j = 0; j < 8; j++) {
            float2 p = upk2(acc[i][j]);
            C[m * HH + n0 + tx + 16 * j] = p.x + p.y + bias8[j];
        }
    }
}

// =======================================================================
// Recurrence with DSMEM exchange.
// 16 clusters x 8 CTAs. Cluster owns 4 batch chains; CTA owns 64 output cols.
// Per step: compute slice from smem h (double-buffered), reduce, push results
// via st.shared::cluster into all 8 peers' next-step h buffer, signal via
// per-buffer mbarrier (8 arrivals), acquire-wait, repeat. No L2 round trip,
// no aligned cluster barrier in the loop.
// =======================================================================
__global__ void __launch_bounds__(256, 1) __cluster_dims__(8, 1, 1)
rnn_recur(const float* __restrict__ xp, const float* __restrict__ Whh,
          float* __restrict__ ys)
{
    __shared__ ulonglong2 h_s[2][4][HH / 4];  // double-buffered h: 2 x 8KB
    __shared__ float4 redv[8][64];            // cross-warp k reduction
    __shared__ float out_s[4][64];            // staged results [batch][col]
    __shared__ u64 mbar[2];

    const int tid   = threadIdx.x;
    const int r     = blockIdx.x & 7;        // cluster rank
    const int cl    = blockIdx.x >> 3;
    const int bg    = cl * 4;
    const int jbase = r * 64;

    const int jp = tid & 31;                  // col-pair slot (j, j+32)
    const int kc = tid >> 5;                  // k-chunk 0..7
    const int k0 = kc * 64;

    // ---- W_hh slice in registers, k-pair packed ----
    u64 w[2][32];
    #pragma unroll
    for (int jj = 0; jj < 2; jj++) {
        const float* wrow = &Whh[(size_t)(jbase + jp + jj * 32) * HH + k0];
        #pragma unroll
        for (int kp = 0; kp < 32; kp++) {
            float2 wv = *(const float2*)&wrow[2 * kp];
            w[jj][kp] = pk2(wv.x, wv.y);
        }
    }

    // ---- init: zero h buffer 0, init mbarriers ----
    {
        float4* hs = (float4*)h_s;
        for (int i = tid; i < 2 * 4 * (HH / 4); i += 256)
            hs[i] = make_float4(0.f, 0.f, 0.f, 0.f);
    }
    const uint32_t mb_addr0 = smem_u32(&mbar[0]);
    const uint32_t mb_addr1 = smem_u32(&mbar[1]);
    if (tid == 0) {
        mbar_init(mb_addr0, 8);
        mbar_init(mb_addr1, 8);
    }
    __syncthreads();
    cluster_sync_full();   // peers' mbarriers + buffers ready before any remote op

    // ---- writer setup (tid < 64): one float4 = 4 cols of one batch ----
    const int wb  = tid >> 4;                 // batch 0..3
    const int wc4 = tid & 15;                 // col group 0..15
    uint32_t peer_addr[8];
    float* ys_w = nullptr;
    if (tid < 64) {
        const uint32_t hbase = smem_u32(&h_s[0][0][0]);
        const uint32_t local_off = (uint32_t)(wb * (HH * 4) + (jbase + wc4 * 4) * 4);
        #pragma unroll
        for (int q = 0; q < 8; q++)
            peer_addr[q] = mapa_u32(hbase, q) + local_off;
        ys_w = &ys[((size_t)(bg + wb) * TT) * HH + jbase + wc4 * 4];
    }
    uint32_t my_arr0 = 0, my_arr1 = 0;
    if (tid < 8) {
        my_arr0 = mapa_u32(mb_addr0, tid);
        my_arr1 = mapa_u32(mb_addr1, tid);
    }

    // consumer mapping: one output scalar per thread
    const int cb = tid & 3;
    const int cj = tid >> 2;
    const float* xp_ptr = &xp[((size_t)(bg + cb) * TT) * HH + jbase + cj];

    for (int t = 0; t < TT; t++) {
        const float xpv = __ldg(xp_ptr);

        // ---- partial GEMM: W from regs, h broadcast from smem buffer t&1 ----
        const ulonglong2* hb = &h_s[t & 1][0][0];
        u64 acc0[4], acc1[4];
        #pragma unroll
        for (int b = 0; b < 4; b++) {
            u64 a0 = 0ull, a1 = 0ull;
            #pragma unroll
            for (int kv = 0; kv < 16; kv++) {
                ulonglong2 hv = hb[b * (HH / 4) + kc * 16 + kv];
                fma2(a0, w[0][2 * kv],     hv.x);
                fma2(a0, w[0][2 * kv + 1], hv.y);
                fma2(a1, w[1][2 * kv],     hv.x);
                fma2(a1, w[1][2 * kv + 1], hv.y);
            }
            acc0[b] = a0; acc1[b] = a1;
        }

        // ---- cross-warp reduction staging ----
        {
            float4 v0, v1;
            float2 p;
            p = upk2(acc0[0]); v0.x = p.x + p.y;
            p = upk2(acc0[1]); v0.y = p.x + p.y;
            p = upk2(acc0[2]); v0.z = p.x + p.y;
            p = upk2(acc0[3]); v0.w = p.x + p.y;
            p = upk2(acc1[0]); v1.x = p.x + p.y;
            p = upk2(acc1[1]); v1.y = p.x + p.y;
            p = upk2(acc1[2]); v1.z = p.x + p.y;
            p = upk2(acc1[3]); v1.w = p.x + p.y;
            redv[kc][jp]      = v0;
            redv[kc][jp + 32] = v1;
        }
        __syncthreads();

        // ---- reduce 8 partials, add xproj, relu, stage ----
        {
            const float* rp = (const float*)redv;
            float s = 0.f;
            #pragma unroll
            for (int c = 0; c < 8; c++) s += rp[c * 256 + cj * 4 + cb];
            s += xpv;
            s = fmaxf(s, 0.f);
            out_s[cb][cj] = s;
        }
        __syncthreads();

        // ---- DSMEM push of this CTA's slice into all peers' next buffer ----
        const int wbuf = (t + 1) & 1;
        if (tid < 64) {
            const float4 v = ((const float4*)out_s)[tid];
            const uint32_t boff = (uint32_t)wbuf * (4 * HH * 4);
            #pragma unroll
            for (int q = 0; q < 8; q++)
                st_dsmem4(peer_addr[q] + boff, v);
            *(float4*)ys_w = v;          // for next layer / projection
            ys_w += HH;
        }
        __syncthreads();                 // all writers done before release-arrive

        if (tid < 8)
            mbar_arrive_remote(wbuf ? my_arr1 : my_arr0);

        // ---- wait for all 8 CTAs' slices for step t+1 ----
        mbar_wait_cluster(wbuf ? mb_addr1 : mb_addr0, (t >> 1) & 1);

        xp_ptr += HH;
    }

    cluster_sync_full();   // no CTA exits while cluster traffic may be in flight
}

// =======================================================================
// Final projection
// =======================================================================
__global__ void proj_kernel(const float* __restrict__ ys,
                            const float* __restrict__ Wout,
                            const float* __restrict__ bout,
                            float* __restrict__ out)
{
    const int b    = blockIdx.x;
    const int c    = threadIdx.y;
    const int lane = threadIdx.x;
    const float* hrow = &ys[((size_t)b * TT + (TT - 1)) * HH];
    const float* wrow = &Wout[(size_t)c * HH];
    float s = 0.f;
    for (int k = lane; k < HH; k += 32) s += hrow[k] * wrow[k];
    #pragma unroll
    for (int o = 16; o > 0; o >>= 1) s += __shfl_down_sync(0xffffffffu, s, o);
    if (lane == 0) out[b * NCLS + c] = s + bout[c];
}

// =======================================================================
extern "C" void kernel_launch(void* const* d_in, const int* in_sizes, int n_in,
                              void* d_out, int out_size)
{
    (void)in_sizes; (void)n_in; (void)out_size;
    const float* x    = (const float*)d_in[0];
    const float* Wih[3] = {(const float*)d_in[1], (const float*)d_in[5], (const float*)d_in[9]};
    const float* Whh[3] = {(const float*)d_in[2], (const float*)d_in[6], (const float*)d_in[10]};
    const float* bih[3] = {(const float*)d_in[3], (const float*)d_in[7], (const float*)d_in[11]};
    const float* bhh[3] = {(const float*)d_in[4], (const float*)d_in[8], (const float*)d_in[12]};
    const float* Wout = (const float*)d_in[13];
    const float* bout = (const float*)d_in[14];
    float* out = (float*)d_out;

    float *xpPtr = nullptr, *ysPtr = nullptr;
    cudaGetSymbolAddress((void**)&xpPtr, g_xp);
    cudaGetSymbolAddress((void**)&ysPtr, g_ys);

    const dim3 ggrid(HH / 128, (BB * TT) / 128);
    for (int l = 0; l < 3; l++) {
        const float* A = (l == 0) ? x : ysPtr;
        const int K = (l == 0) ? II : HH;
        gemm_xproj<<<ggrid, 256>>>(A, Wih[l], bih[l], bhh[l], xpPtr, K);
        rnn_recur<<<128, 256>>>(xpPtr, Whh[l], ysPtr);
    }
    proj_kernel<<<64, dim3(32, 5)>>>(ysPtr, Wout, bout, out);
}

// round 3
// speedup vs baseline: 1.2189x; 1.0539x over previous
#include <cuda_runtime.h>
#include <cstdint>
#include <cstddef>

#define BB 64
#define TT 512
#define II 128
#define HH 512
#define NCLS 5

typedef unsigned long long u64;

// Scratch — static __device__ arrays per allocation rules.
__device__ float g_xp[(size_t)BB * TT * HH];
__device__ float g_ys[(size_t)BB * TT * HH];

// ---------------- packed f32x2 helpers ----------------
__device__ __forceinline__ u64 pk2(float x, float y) {
    u64 r; asm("mov.b64 %0, {%1,%2};" : "=l"(r) : "f"(x), "f"(y)); return r;
}
__device__ __forceinline__ float2 upk2(u64 v) {
    float2 f; asm("mov.b64 {%0,%1}, %2;" : "=f"(f.x), "=f"(f.y) : "l"(v)); return f;
}
__device__ __forceinline__ void fma2(u64 &d, u64 a, u64 b) {
    asm("fma.rn.f32x2 %0, %1, %2, %0;" : "+l"(d) : "l"(a), "l"(b));
}

// ---------------- cluster / mbarrier helpers ----------------
__device__ __forceinline__ uint32_t smem_u32(const void* p) {
    uint32_t a;
    asm("{ .reg .u64 t; cvta.to.shared.u64 t, %1; cvt.u32.u64 %0, t; }"
        : "=r"(a) : "l"(p));
    return a;
}
__device__ __forceinline__ uint32_t mapa_u32(uint32_t local, uint32_t rank) {
    uint32_t r;
    asm("mapa.shared::cluster.u32 %0, %1, %2;" : "=r"(r) : "r"(local), "r"(rank));
    return r;
}
__device__ __forceinline__ void mbar_init(uint32_t addr, uint32_t count) {
    asm volatile("mbarrier.init.shared.b64 [%0], %1;" :: "r"(addr), "r"(count) : "memory");
}
__device__ __forceinline__ void mbar_expect_tx(uint32_t addr, uint32_t bytes) {
    asm volatile("mbarrier.arrive.expect_tx.shared.b64 _, [%0], %1;"
                 :: "r"(addr), "r"(bytes) : "memory");
}
__device__ __forceinline__ void bulk_copy_cluster(uint32_t dst_cluster, uint32_t src_cta,
                                                  uint32_t bytes, uint32_t mbar_cluster) {
    asm volatile("cp.async.bulk.shared::cluster.shared::cta.mbarrier::complete_tx::bytes "
                 "[%0], [%1], %2, [%3];"
                 :: "r"(dst_cluster), "r"(src_cta), "r"(bytes), "r"(mbar_cluster) : "memory");
}
__device__ __forceinline__ void mbar_wait_cluster(uint32_t addr, uint32_t parity) {
    asm volatile(
        "{\n\t"
        ".reg .pred P;\n\t"
        "WLP%=:\n\t"
        "mbarrier.try_wait.parity.acquire.cluster.shared::cta.b64 P, [%0], %1, 0x989680;\n\t"
        "@P bra WDN%=;\n\t"
        "bra WLP%=;\n\t"
        "WDN%=:\n\t"
        "}"
        :: "r"(addr), "r"(parity) : "memory");
}
__device__ __forceinline__ void fence_proxy_async_cta() {
    asm volatile("fence.proxy.async.shared::cta;" ::: "memory");
}
__device__ __forceinline__ void cluster_sync_full() {
    asm volatile("barrier.cluster.arrive.aligned;" ::: "memory");
    asm volatile("barrier.cluster.wait.aligned;" ::: "memory");
}

// =======================================================================
// GEMM: C[M][HH] = A[M][K] @ W[HH][K]^T + b1 + b2
// =======================================================================
__global__ void __launch_bounds__(256, 1)
gemm_xproj(const float* __restrict__ A, const float* __restrict__ W,
           const float* __restrict__ b1, const float* __restrict__ b2,
           float* __restrict__ C, int K)
{
    __shared__ u64 As2[8][128];
    __shared__ u64 Bs2[8][128];

    const int tid = threadIdx.x;
    const int m0 = blockIdx.y * 128;
    const int n0 = blockIdx.x * 128;
    const int tx = tid & 15;
    const int ty = tid >> 4;

    const int r0  = tid >> 2;
    const int kq0 = tid & 3;

    u64 acc[8][8];
    #pragma unroll
    for (int i = 0; i < 8; i++)
        #pragma unroll
        for (int j = 0; j < 8; j++) acc[i][j] = 0ull;

    const int ktiles = K >> 4;
    for (int kt = 0; kt < ktiles; kt++) {
        const int kb = kt * 16;
        float4 a0 = *(const float4*)&A[(size_t)(m0 + r0)      * K + kb + kq0 * 4];
        float4 a1 = *(const float4*)&A[(size_t)(m0 + 64 + r0) * K + kb + kq0 * 4];
        float4 w0 = *(const float4*)&W[(size_t)(n0 + r0)      * K + kb + kq0 * 4];
        float4 w1 = *(const float4*)&W[(size_t)(n0 + 64 + r0) * K + kb + kq0 * 4];
        __syncthreads();
        As2[kq0 * 2][r0]          = pk2(a0.x, a0.y);
        As2[kq0 * 2 + 1][r0]      = pk2(a0.z, a0.w);
        As2[kq0 * 2][64 + r0]     = pk2(a1.x, a1.y);
        As2[kq0 * 2 + 1][64 + r0] = pk2(a1.z, a1.w);
        Bs2[kq0 * 2][r0]          = pk2(w0.x, w0.y);
        Bs2[kq0 * 2 + 1][r0]      = pk2(w0.z, w0.w);
        Bs2[kq0 * 2][64 + r0]     = pk2(w1.x, w1.y);
        Bs2[kq0 * 2 + 1][64 + r0] = pk2(w1.z, w1.w);
        __syncthreads();

        #pragma unroll
        for (int k2 = 0; k2 < 8; k2++) {
            u64 af[8], bf[8];
            #pragma unroll
            for (int i = 0; i < 8; i++) af[i] = As2[k2][ty + 16 * i];
            #pragma unroll
            for (int j = 0; j < 8; j++) bf[j] = Bs2[k2][tx + 16 * j];
            #pragma unroll
            for (int i = 0; i < 8; i++)
                #pragma unroll
                for (int j = 0; j < 8; j++)
                    fma2(acc[i][j], af[i], bf[j]);
        }
    }

    float bias8[8];
    #pragma unroll
    for (int j = 0; j < 8; j++) {
        int n = n0 + tx + 16 * j;
        bias8[j] = b1[n] + b2[n];
    }
    #pragma unroll
    for (int i = 0; i < 8; i++) {
        const size_t m = (size_t)(m0 + ty + 16 * i);
        #pragma unroll
        for (int j = 0; j < 8; j++) {
            float2 p = upk2(acc[i][j]);
            C[m * HH + n0 + tx + 16 * j] = p.x + p.y + bias8[j];
        }
    }
}

// =======================================================================
// Recurrence with async bulk DSMEM exchange.
// 16 clusters x 8 CTAs. CTA r owns output cols [64r, 64r+64) of 4 batch chains.
// h layout: h_s[buf][chunk(=producer rank)][batch][64 cols] so each producer's
// contribution is ONE contiguous 1KB block per consumer. Per step, one elected
// thread issues 8 cp.async.bulk copies (1KB each) of the freshly computed
// slice into all peers' next h buffer; completion is tx-counted on the
// consumer's mbarrier (expect_tx 8192, arrive count 1).
// =======================================================================
__global__ void __launch_bounds__(256, 1) __cluster_dims__(8, 1, 1)
rnn_recur(const float* __restrict__ xp, const float* __restrict__ Whh,
          float* __restrict__ ys)
{
    __shared__ ulonglong2 h_s[2][8][4][16];       // [buf][chunk][batch][64 floats]
    __shared__ float4 redv[8][64];                // cross-warp k reduction
    __shared__ __align__(16) float out_s[2][4][64]; // double-buffered slice
    __shared__ u64 mbar[2];

    const int tid   = threadIdx.x;
    const int r     = blockIdx.x & 7;             // cluster rank
    const int cl    = blockIdx.x >> 3;
    const int bg    = cl * 4;
    const int jbase = r * 64;

    const int jp = tid & 31;                      // col-pair slot (j, j+32)
    const int kc = tid >> 5;                      // k-chunk 0..7
    const int k0 = kc * 64;

    // ---- W_hh slice in registers, k-pair packed ----
    u64 w[2][32];
    #pragma unroll
    for (int jj = 0; jj < 2; jj++) {
        const float* wrow = &Whh[(size_t)(jbase + jp + jj * 32) * HH + k0];
        #pragma unroll
        for (int kp = 0; kp < 32; kp++) {
            float2 wv = *(const float2*)&wrow[2 * kp];
            w[jj][kp] = pk2(wv.x, wv.y);
        }
    }

    // ---- init: zero h buffers, init mbarriers ----
    {
        float4* hs = (float4*)h_s;
        for (int i = tid; i < 2 * 8 * 4 * 16; i += 256)
            hs[i] = make_float4(0.f, 0.f, 0.f, 0.f);
    }
    const uint32_t mb_addr[2] = { smem_u32(&mbar[0]), smem_u32(&mbar[1]) };
    const uint32_t hbase = smem_u32(&h_s[0][0][0][0]);
    const uint32_t obase = smem_u32(&out_s[0][0][0]);
    if (tid == 0) {
        mbar_init(mb_addr[0], 1);
        mbar_init(mb_addr[1], 1);
    }
    __syncthreads();
    cluster_sync_full();   // peers' mbarriers + buffers ready before any remote op

    // ---- ys writer mapping (tid < 64): one float4 = 4 cols of one batch ----
    const int wb  = tid >> 4;
    const int wc4 = tid & 15;
    float* ys_w = &ys[((size_t)(bg + wb) * TT) * HH + jbase + wc4 * 4];

    // consumer mapping: one output scalar per thread
    const int cb = tid & 3;
    const int cj = tid >> 2;
    const float* xp_ptr = &xp[((size_t)(bg + cb) * TT) * HH + jbase + cj];

    for (int t = 0; t < TT; t++) {
        const int os   = t & 1;
        const int wbuf = (t + 1) & 1;
        const bool push = (t + 1 < TT);

        // announce expected inbound bytes for next step's buffer
        if (tid == 0 && push)
            mbar_expect_tx(mb_addr[wbuf], 8 * 1024u);

        const float xpv = __ldg(xp_ptr);

        // ---- partial GEMM: W from regs, h broadcast from smem ----
        const ulonglong2* hb = &h_s[os][kc][0][0];
        u64 acc0[4], acc1[4];
        #pragma unroll
        for (int b = 0; b < 4; b++) {
            u64 a0 = 0ull, a1 = 0ull;
            #pragma unroll
            for (int kv = 0; kv < 16; kv++) {
                ulonglong2 hv = hb[b * 16 + kv];
                fma2(a0, w[0][2 * kv],     hv.x);
                fma2(a0, w[0][2 * kv + 1], hv.y);
                fma2(a1, w[1][2 * kv],     hv.x);
                fma2(a1, w[1][2 * kv + 1], hv.y);
            }
            acc0[b] = a0; acc1[b] = a1;
        }

        // ---- cross-warp reduction staging ----
        {
            float4 v0, v1;
            float2 p;
            p = upk2(acc0[0]); v0.x = p.x + p.y;
            p = upk2(acc0[1]); v0.y = p.x + p.y;
            p = upk2(acc0[2]); v0.z = p.x + p.y;
            p = upk2(acc0[3]); v0.w = p.x + p.y;
            p = upk2(acc1[0]); v1.x = p.x + p.y;
            p = upk2(acc1[1]); v1.y = p.x + p.y;
            p = upk2(acc1[2]); v1.z = p.x + p.y;
            p = upk2(acc1[3]); v1.w = p.x + p.y;
            redv[kc][jp]      = v0;
            redv[kc][jp + 32] = v1;
        }
        __syncthreads();

        // ---- reduce 8 partials, add xproj, relu, stage into out_s[os] ----
        {
            const float* rp = (const float*)redv;
            float s = 0.f;
            #pragma unroll
            for (int c = 0; c < 8; c++) s += rp[c * 256 + cj * 4 + cb];
            s += xpv;
            out_s[os][cb][cj] = fmaxf(s, 0.f);
        }
        __syncthreads();

        // ---- global ys write (async wrt exchange) ----
        if (tid < 64) {
            const float4 v = ((const float4*)&out_s[os][0][0])[tid];
            *(float4*)ys_w = v;
            ys_w += HH;
        }

        // ---- async bulk push of this CTA's 1KB slice into all peers ----
        if (tid == 0 && push) {
            fence_proxy_async_cta();
            const uint32_t src  = obase + (uint32_t)os * 1024u;
            const uint32_t doff = (uint32_t)wbuf * 8192u + (uint32_t)r * 1024u;
            const uint32_t mb   = mb_addr[wbuf];
            #pragma unroll
            for (int q = 0; q < 8; q++) {
                const uint32_t dst = mapa_u32(hbase, q) + doff;
                const uint32_t rmb = mapa_u32(mb, q);
                bulk_copy_cluster(dst, src, 1024u, rmb);
            }
        }

        // ---- wait for all 8 slices of step t+1 ----
        if (push)
            mbar_wait_cluster(mb_addr[wbuf], (t >> 1) & 1);

        xp_ptr += HH;
    }

    cluster_sync_full();   // all inbound traffic delivered before any CTA exits
}

// =======================================================================
// Final projection
// =======================================================================
__global__ void proj_kernel(const float* __restrict__ ys,
                            const float* __restrict__ Wout,
                            const float* __restrict__ bout,
                            float* __restrict__ out)
{
    const int b    = blockIdx.x;
    const int c    = threadIdx.y;
    const int lane = threadIdx.x;
    const float* hrow = &ys[((size_t)b * TT + (TT - 1)) * HH];
    const float* wrow = &Wout[(size_t)c * HH];
    float s = 0.f;
    for (int k = lane; k < HH; k += 32) s += hrow[k] * wrow[k];
    #pragma unroll
    for (int o = 16; o > 0; o >>= 1) s += __shfl_down_sync(0xffffffffu, s, o);
    if (lane == 0) out[b * NCLS + c] = s + bout[c];
}

// =======================================================================
extern "C" void kernel_launch(void* const* d_in, const int* in_sizes, int n_in,
                              void* d_out, int out_size)
{
    (void)in_sizes; (void)n_in; (void)out_size;
    const float* x    = (const float*)d_in[0];
    const float* Wih[3] = {(const float*)d_in[1], (const float*)d_in[5], (const float*)d_in[9]};
    const float* Whh[3] = {(const float*)d_in[2], (const float*)d_in[6], (const float*)d_in[10]};
    const float* bih[3] = {(const float*)d_in[3], (const float*)d_in[7], (const float*)d_in[11]};
    const float* bhh[3] = {(const float*)d_in[4], (const float*)d_in[8], (const float*)d_in[12]};
    const float* Wout = (const float*)d_in[13];
    const float* bout = (const float*)d_in[14];
    float* out = (float*)d_out;

    float *xpPtr = nullptr, *ysPtr = nullptr;
    cudaGetSymbolAddress((void**)&xpPtr, g_xp);
    cudaGetSymbolAddress((void**)&ysPtr, g_ys);

    const dim3 ggrid(HH / 128, (BB * TT) / 128);
    for (int l = 0; l < 3; l++) {
        const float* A = (l == 0) ? x : ysPtr;
        const int K = (l == 0) ? II : HH;
        gemm_xproj<<<ggrid, 256>>>(A, Wih[l], bih[l], bhh[l], xpPtr, K);
        rnn_recur<<<128, 256>>>(xpPtr, Whh[l], ysPtr);
    }
    proj_kernel<<<64, dim3(32, 5)>>>(ysPtr, Wout, bout, out);
}

// round 4
// speedup vs baseline: 1.6678x; 1.3683x over previous
#include <cuda_runtime.h>
#include <cstdint>
#include <cstddef>

#define BB 64
#define TT 512
#define II 128
#define HH 512
#define NCLS 5

typedef unsigned long long u64;

// Scratch — static __device__ arrays per allocation rules.
__device__ float g_xp[(size_t)BB * TT * HH];
__device__ float g_ys[(size_t)BB * TT * HH];

// ---------------- packed f32x2 helpers ----------------
__device__ __forceinline__ u64 pk2(float x, float y) {
    u64 r; asm("mov.b64 %0, {%1,%2};" : "=l"(r) : "f"(x), "f"(y)); return r;
}
__device__ __forceinline__ float2 upk2(u64 v) {
    float2 f; asm("mov.b64 {%0,%1}, %2;" : "=f"(f.x), "=f"(f.y) : "l"(v)); return f;
}
__device__ __forceinline__ void fma2(u64 &d, u64 a, u64 b) {
    asm("fma.rn.f32x2 %0, %1, %2, %0;" : "+l"(d) : "l"(a), "l"(b));
}

// ---------------- cluster / mbarrier helpers ----------------
__device__ __forceinline__ uint32_t smem_u32(const void* p) {
    uint32_t a;
    asm("{ .reg .u64 t; cvta.to.shared.u64 t, %1; cvt.u32.u64 %0, t; }"
        : "=r"(a) : "l"(p));
    return a;
}
__device__ __forceinline__ uint32_t mapa_u32(uint32_t local, uint32_t rank) {
    uint32_t r;
    asm("mapa.shared::cluster.u32 %0, %1, %2;" : "=r"(r) : "r"(local), "r"(rank));
    return r;
}
__device__ __forceinline__ void mbar_init(uint32_t addr, uint32_t count) {
    asm volatile("mbarrier.init.shared.b64 [%0], %1;" :: "r"(addr), "r"(count) : "memory");
}
__device__ __forceinline__ void mbar_expect_tx(uint32_t addr, uint32_t bytes) {
    asm volatile("mbarrier.arrive.expect_tx.shared.b64 _, [%0], %1;"
                 :: "r"(addr), "r"(bytes) : "memory");
}
__device__ __forceinline__ void bulk_copy_cluster(uint32_t dst_cluster, uint32_t src_cta,
                                                  uint32_t bytes, uint32_t mbar_cluster) {
    asm volatile("cp.async.bulk.shared::cluster.shared::cta.mbarrier::complete_tx::bytes "
                 "[%0], [%1], %2, [%3];"
                 :: "r"(dst_cluster), "r"(src_cta), "r"(bytes), "r"(mbar_cluster) : "memory");
}
__device__ __forceinline__ void mbar_wait_cluster(uint32_t addr, uint32_t parity) {
    asm volatile(
        "{\n\t"
        ".reg .pred P;\n\t"
        "WLP%=:\n\t"
        "mbarrier.try_wait.parity.acquire.cluster.shared::cta.b64 P, [%0], %1, 0x989680;\n\t"
        "@P bra WDN%=;\n\t"
        "bra WLP%=;\n\t"
        "WDN%=:\n\t"
        "}"
        :: "r"(addr), "r"(parity) : "memory");
}
__device__ __forceinline__ void fence_proxy_async_cta() {
    asm volatile("fence.proxy.async.shared::cta;" ::: "memory");
}
__device__ __forceinline__ void cluster_sync_full() {
    asm volatile("barrier.cluster.arrive.aligned;" ::: "memory");
    asm volatile("barrier.cluster.wait.aligned;" ::: "memory");
}

// =======================================================================
// GEMM: C[M][HH] = A[M][K] @ W[HH][K]^T + b1 + b2
// =======================================================================
__global__ void __launch_bounds__(256, 1)
gemm_xproj(const float* __restrict__ A, const float* __restrict__ W,
           const float* __restrict__ b1, const float* __restrict__ b2,
           float* __restrict__ C, int K)
{
    __shared__ u64 As2[8][128];
    __shared__ u64 Bs2[8][128];

    const int tid = threadIdx.x;
    const int m0 = blockIdx.y * 128;
    const int n0 = blockIdx.x * 128;
    const int tx = tid & 15;
    const int ty = tid >> 4;

    const int r0  = tid >> 2;
    const int kq0 = tid & 3;

    u64 acc[8][8];
    #pragma unroll
    for (int i = 0; i < 8; i++)
        #pragma unroll
        for (int j = 0; j < 8; j++) acc[i][j] = 0ull;

    const int ktiles = K >> 4;
    for (int kt = 0; kt < ktiles; kt++) {
        const int kb = kt * 16;
        float4 a0 = *(const float4*)&A[(size_t)(m0 + r0)      * K + kb + kq0 * 4];
        float4 a1 = *(const float4*)&A[(size_t)(m0 + 64 + r0) * K + kb + kq0 * 4];
        float4 w0 = *(const float4*)&W[(size_t)(n0 + r0)      * K + kb + kq0 * 4];
        float4 w1 = *(const float4*)&W[(size_t)(n0 + 64 + r0) * K + kb + kq0 * 4];
        __syncthreads();
        As2[kq0 * 2][r0]          = pk2(a0.x, a0.y);
        As2[kq0 * 2 + 1][r0]      = pk2(a0.z, a0.w);
        As2[kq0 * 2][64 + r0]     = pk2(a1.x, a1.y);
        As2[kq0 * 2 + 1][64 + r0] = pk2(a1.z, a1.w);
        Bs2[kq0 * 2][r0]          = pk2(w0.x, w0.y);
        Bs2[kq0 * 2 + 1][r0]      = pk2(w0.z, w0.w);
        Bs2[kq0 * 2][64 + r0]     = pk2(w1.x, w1.y);
        Bs2[kq0 * 2 + 1][64 + r0] = pk2(w1.z, w1.w);
        __syncthreads();

        #pragma unroll
        for (int k2 = 0; k2 < 8; k2++) {
            u64 af[8], bf[8];
            #pragma unroll
            for (int i = 0; i < 8; i++) af[i] = As2[k2][ty + 16 * i];
            #pragma unroll
            for (int j = 0; j < 8; j++) bf[j] = Bs2[k2][tx + 16 * j];
            #pragma unroll
            for (int i = 0; i < 8; i++)
                #pragma unroll
                for (int j = 0; j < 8; j++)
                    fma2(acc[i][j], af[i], bf[j]);
        }
    }

    float bias8[8];
    #pragma unroll
    for (int j = 0; j < 8; j++) {
        int n = n0 + tx + 16 * j;
        bias8[j] = b1[n] + b2[n];
    }
    #pragma unroll
    for (int i = 0; i < 8; i++) {
        const size_t m = (size_t)(m0 + ty + 16 * i);
        #pragma unroll
        for (int j = 0; j < 8; j++) {
            float2 p = upk2(acc[i][j]);
            C[m * HH + n0 + tx + 16 * j] = p.x + p.y + bias8[j];
        }
    }
}

// =======================================================================
// Recurrence with per-chunk async DSMEM exchange.
// 16 clusters x 8 CTAs; CTA r owns output cols [64r,64r+64) of 4 batches.
// h_s[buf][chunk][batch][64]: producer rank c's slice IS chunk c. Warp kc
// consumes exactly chunk kc -> per-chunk mbarriers let each warp start as
// soon as ITS chunk lands (own chunk = 38-cyc self-copy). Copies issued by
// 8 parallel threads; expect_tx posts distributed per-warp, one phase ahead.
// =======================================================================
__global__ void __launch_bounds__(256, 1) __cluster_dims__(8, 1, 1)
rnn_recur(const float* __restrict__ xp, const float* __restrict__ Whh,
          float* __restrict__ ys)
{
    __shared__ ulonglong2 h_s[2][8][4][16];         // [buf][chunk][batch][64 floats]
    __shared__ float4 redv[8][64];                  // cross-warp k reduction
    __shared__ __align__(16) float out_s[2][4][64]; // double-buffered slice
    __shared__ __align__(8) u64 mbar[2][8];         // [buf][chunk]

    const int tid   = threadIdx.x;
    const int r     = blockIdx.x & 7;               // cluster rank
    const int cl    = blockIdx.x >> 3;
    const int bg    = cl * 4;
    const int jbase = r * 64;

    const int jp = tid & 31;                        // col-pair slot (j, j+32)
    const int kc = tid >> 5;                        // k-chunk 0..7 == warp id
    const int k0 = kc * 64;

    // ---- W_hh slice in registers, k-pair packed ----
    u64 w[2][32];
    #pragma unroll
    for (int jj = 0; jj < 2; jj++) {
        const float* wrow = &Whh[(size_t)(jbase + jp + jj * 32) * HH + k0];
        #pragma unroll
        for (int kp = 0; kp < 32; kp++) {
            float2 wv = *(const float2*)&wrow[2 * kp];
            w[jj][kp] = pk2(wv.x, wv.y);
        }
    }

    // ---- init: zero h buffers, init per-chunk mbarriers + first expects ----
    {
        float4* hs = (float4*)h_s;
        for (int i = tid; i < 2 * 8 * 4 * 16; i += 256)
            hs[i] = make_float4(0.f, 0.f, 0.f, 0.f);
    }
    const uint32_t mb_base = smem_u32(&mbar[0][0]);
    const uint32_t hbase   = smem_u32(&h_s[0][0][0][0]);
    const uint32_t obase   = smem_u32(&out_s[0][0][0]);
    if (tid < 16) {
        mbar_init(mb_base + tid * 8u, 1);
        mbar_expect_tx(mb_base + tid * 8u, 1024u);   // first phase of each mbar
    }
    __syncthreads();
    cluster_sync_full();   // peers' mbarriers + buffers ready before any remote op

    // my-warp mbarrier addresses (chunk = kc) for buf 0/1
    const uint32_t my_mb[2] = { mb_base + (uint32_t)kc * 8u,
                                mb_base + (uint32_t)(8 + kc) * 8u };
    int par0 = 0, par1 = 0;   // per-warp phase parity for buf0/buf1 waits

    // producer copy targets (tid < 8): peer q = tid, chunk = my rank r
    uint32_t dst_peer0 = 0, dst_peer1 = 0, rmb0 = 0, rmb1 = 0;
    if (tid < 8) {
        const uint32_t q = (uint32_t)tid;
        dst_peer0 = mapa_u32(hbase, q) + (uint32_t)r * 1024u;            // buf0
        dst_peer1 = dst_peer0 + 8192u;                                   // buf1
        rmb0 = mapa_u32(mb_base + (uint32_t)r * 8u, q);
        rmb1 = mapa_u32(mb_base + (uint32_t)(8 + r) * 8u, q);
    }

    // ---- ys writer mapping (tid < 64) ----
    const int wb  = tid >> 4;
    const int wc4 = tid & 15;
    float* ys_w = &ys[((size_t)(bg + wb) * TT) * HH + jbase + wc4 * 4];

    // consumer mapping: one output scalar per thread
    const int cb = tid & 3;
    const int cj = tid >> 2;
    const float* xp_ptr = &xp[((size_t)(bg + cb) * TT) * HH + jbase + cj];

    const bool lane0 = (jp == 0);

    for (int t = 0; t < TT; t++) {
        const int os = t & 1;

        const float xpv = __ldg(xp_ptr);

        // ---- per-warp wait for MY chunk only (skip t=0: zeros) ----
        if (t > 0) {
            if (os == 0) {
                mbar_wait_cluster(my_mb[0], par0);
                if (lane0) mbar_expect_tx(my_mb[0], 1024u);  // next phase, 2 steps out
                par0 ^= 1;
            } else {
                mbar_wait_cluster(my_mb[1], par1);
                if (lane0) mbar_expect_tx(my_mb[1], 1024u);
                par1 ^= 1;
            }
        }

        // ---- partial GEMM: W from regs, h broadcast from smem chunk kc ----
        const ulonglong2* hb = &h_s[os][kc][0][0];
        u64 acc0[4], acc1[4];
        #pragma unroll
        for (int b = 0; b < 4; b++) {
            u64 a0 = 0ull, a1 = 0ull;
            #pragma unroll
            for (int kv = 0; kv < 16; kv++) {
                ulonglong2 hv = hb[b * 16 + kv];
                fma2(a0, w[0][2 * kv],     hv.x);
                fma2(a0, w[0][2 * kv + 1], hv.y);
                fma2(a1, w[1][2 * kv],     hv.x);
                fma2(a1, w[1][2 * kv + 1], hv.y);
            }
            acc0[b] = a0; acc1[b] = a1;
        }

        // ---- cross-warp reduction staging ----
        {
            float4 v0, v1;
            float2 p;
            p = upk2(acc0[0]); v0.x = p.x + p.y;
            p = upk2(acc0[1]); v0.y = p.x + p.y;
            p = upk2(acc0[2]); v0.z = p.x + p.y;
            p = upk2(acc0[3]); v0.w = p.x + p.y;
            p = upk2(acc1[0]); v1.x = p.x + p.y;
            p = upk2(acc1[1]); v1.y = p.x + p.y;
            p = upk2(acc1[2]); v1.z = p.x + p.y;
            p = upk2(acc1[3]); v1.w = p.x + p.y;
            redv[kc][jp]      = v0;
            redv[kc][jp + 32] = v1;
        }
        __syncthreads();

        // ---- reduce 8 partials, add xproj, relu, stage into out_s[os] ----
        {
            const float* rp = (const float*)redv;
            float s = 0.f;
            #pragma unroll
            for (int c = 0; c < 8; c++) s += rp[c * 256 + cj * 4 + cb];
            s += xpv;
            out_s[os][cb][cj] = fmaxf(s, 0.f);
        }
        __syncthreads();

        // ---- async push: 8 threads, one 1KB copy each, before ys STG ----
        if (t + 1 < TT && tid < 8) {
            fence_proxy_async_cta();
            const uint32_t src = obase + (uint32_t)os * 1024u;
            if (os == 0)   // next buffer is 1
                bulk_copy_cluster(dst_peer1, src, 1024u, rmb1);
            else           // next buffer is 0
                bulk_copy_cluster(dst_peer0, src, 1024u, rmb0);
        }

        // ---- global ys write (off critical path) ----
        if (tid < 64) {
            const float4 v = ((const float4*)&out_s[os][0][0])[tid];
            *(float4*)ys_w = v;
            ys_w += HH;
        }

        xp_ptr += HH;
    }

    cluster_sync_full();   // all inbound traffic settled before any CTA exits
}

// =======================================================================
// Final projection
// =======================================================================
__global__ void proj_kernel(const float* __restrict__ ys,
                            const float* __restrict__ Wout,
                            const float* __restrict__ bout,
                            float* __restrict__ out)
{
    const int b    = blockIdx.x;
    const int c    = threadIdx.y;
    const int lane = threadIdx.x;
    const float* hrow = &ys[((size_t)b * TT + (TT - 1)) * HH];
    const float* wrow = &Wout[(size_t)c * HH];
    float s = 0.f;
    for (int k = lane; k < HH; k += 32) s += hrow[k] * wrow[k];
    #pragma unroll
    for (int o = 16; o > 0; o >>= 1) s += __shfl_down_sync(0xffffffffu, s, o);
    if (lane == 0) out[b * NCLS + c] = s + bout[c];
}

// =======================================================================
extern "C" void kernel_launch(void* const* d_in, const int* in_sizes, int n_in,
                              void* d_out, int out_size)
{
    (void)in_sizes; (void)n_in; (void)out_size;
    const float* x    = (const float*)d_in[0];
    const float* Wih[3] = {(const float*)d_in[1], (const float*)d_in[5], (const float*)d_in[9]};
    const float* Whh[3] = {(const float*)d_in[2], (const float*)d_in[6], (const float*)d_in[10]};
    const float* bih[3] = {(const float*)d_in[3], (const float*)d_in[7], (const float*)d_in[11]};
    const float* bhh[3] = {(const float*)d_in[4], (const float*)d_in[8], (const float*)d_in[12]};
    const float* Wout = (const float*)d_in[13];
    const float* bout = (const float*)d_in[14];
    float* out = (float*)d_out;

    float *xpPtr = nullptr, *ysPtr = nullptr;
    cudaGetSymbolAddress((void**)&xpPtr, g_xp);
    cudaGetSymbolAddress((void**)&ysPtr, g_ys);

    const dim3 ggrid(HH / 128, (BB * TT) / 128);
    for (int l = 0; l < 3; l++) {
        const float* A = (l == 0) ? x : ysPtr;
        const int K = (l == 0) ? II : HH;
        gemm_xproj<<<ggrid, 256>>>(A, Wih[l], bih[l], bhh[l], xpPtr, K);
        rnn_recur<<<128, 256>>>(xpPtr, Whh[l], ysPtr);
    }
    proj_kernel<<<64, dim3(32, 5)>>>(ysPtr, Wout, bout, out);
}